// round 13
// baseline (speedup 1.0000x reference)
#include <cuda_runtime.h>
#include <cuda_fp16.h>
#include <cstdint>

typedef unsigned int u32;

#define IN_DIM   4096
#define OUT_DIM  4081
#define TILE     128           // square output tile
#define NT_SIDE  32
#define NTILES   1024          // 32 x 32
#define XT_ROWS  144           // 128 + 16 halo
#define XT_STRIDE 304          // bytes per x-tile row (152 halves)
#define NCHUNK   36            // k16 chunks = 72 octets paired

// A: [36 chunks][64 m][24 halves (16 data + 8 pad)] -> 48 B/row, conflict-free ldmatrix
#define A_ROWB   48
#define SZ_A     (NCHUNK * 64 * A_ROWB)     // 110592
#define SZ_X     (XT_ROWS * XT_STRIDE)      // 43776
#define S_A      0
#define S_X      SZ_A
#define SMEM_TOTAL (SZ_A + 2 * SZ_X)        // 198144

__device__ __half g_x16[(size_t)IN_DIM * IN_DIM];
__device__ __half g_A[SZ_A / 2];

__device__ __forceinline__ u32 smem_u32(const void* p) {
    u32 a;
    asm("{ .reg .u64 t; cvta.to.shared.u64 t, %1; cvt.u32.u64 %0, t; }" : "=r"(a) : "l"(p));
    return a;
}

#define LDSM4(r, a) \
    asm volatile("ldmatrix.sync.aligned.m8n8.x4.shared.b16 {%0,%1,%2,%3}, [%4];" \
        : "=r"((r)[0]), "=r"((r)[1]), "=r"((r)[2]), "=r"((r)[3]) : "r"(a))

#define MMA16(d, a, b0, b1) \
    asm volatile("mma.sync.aligned.m16n8k16.row.col.f32.f16.f16.f32 " \
        "{%0,%1,%2,%3}, {%4,%5,%6,%7}, {%8,%9}, {%0,%1,%2,%3};" \
        : "+f"((d)[0]), "+f"((d)[1]), "+f"((d)[2]), "+f"((d)[3]) \
        : "r"((a)[0]), "r"((a)[1]), "r"((a)[2]), "r"((a)[3]), "r"(b0), "r"(b1))

#define CP16(dst, src)  asm volatile("cp.async.cg.shared.global [%0], [%1], 16;" :: "r"(dst), "l"(src))
#define CPCOMMIT()      asm volatile("cp.async.commit_group;" ::: "memory")
#define CPWAIT0()       asm volatile("cp.async.wait_group 0;" ::: "memory")
#define CPWAIT1()       asm volatile("cp.async.wait_group 1;" ::: "memory")

// ============ prep: x fp32 -> fp16 ============
__global__ void convert_x_kernel(const float* __restrict__ x) {
    size_t base = ((size_t)blockIdx.x * 256u + threadIdx.x) * 8u;
    float4 v0 = *reinterpret_cast<const float4*>(x + base);
    float4 v1 = *reinterpret_cast<const float4*>(x + base + 4);
    u32 r[4];
    r[0] = (u32)__half_as_ushort(__float2half(v0.x)) | ((u32)__half_as_ushort(__float2half(v0.y)) << 16);
    r[1] = (u32)__half_as_ushort(__float2half(v0.z)) | ((u32)__half_as_ushort(__float2half(v0.w)) << 16);
    r[2] = (u32)__half_as_ushort(__float2half(v1.x)) | ((u32)__half_as_ushort(__float2half(v1.y)) << 16);
    r[3] = (u32)__half_as_ushort(__float2half(v1.z)) | ((u32)__half_as_ushort(__float2half(v1.w)) << 16);
    *reinterpret_cast<uint4*>(g_x16 + base) = make_uint4(r[0], r[1], r[2], r[3]);
}

// ============ prep: shifted-weight A, k16-paired octets, 48B pitch ============
// chunk c pairs octets (2c, 2c+1); octet o: p = o/3, q = (o%3)*8 + (kk&7)
__global__ void prep_a_kernel(const float* __restrict__ w) {
    int e = blockIdx.x * 256 + threadIdx.x;        // [0, 55296)
    int c   = e / (64 * 24);
    int rem = e - c * (64 * 24);
    int m   = rem / 24;
    int kk  = rem - m * 24;
    float v = 0.0f;
    if (kk < 16) {
        int o  = 2 * c + (kk >> 3);
        int p  = o / 3;
        int q  = (o - p * 3) * 8 + (kk & 7);
        int di = m >> 3, dj = m & 7;
        int pi = p - di, qi = q - dj;
        if (pi >= 0 && pi < 16 && qi >= 0 && qi < 16) v = w[pi * 16 + qi];
    }
    g_A[e] = __float2half(v);
}

// ============ main: persistent k16 implicit-GEMM conv ============
__global__ __launch_bounds__(512, 1)
void conv_hmma_kernel(const float* __restrict__ bias, float* __restrict__ out)
{
    extern __shared__ char sm[];
    const u32 smb  = smem_u32(sm);
    const int tid  = threadIdx.x;
    const int lane = tid & 31;
    const int wid  = tid >> 5;
    const int wm   = wid >> 3;        // 0..1  (M half: m 0-31 / 32-63)
    const int wn   = wid & 7;         // 0..7  (N 32-group)
    const float bv = bias[0];

    // ---- stage A once per CTA lifetime ----
    {
        const uint4* src = reinterpret_cast<const uint4*>(g_A);
        uint4* dst = reinterpret_cast<uint4*>(sm + S_A);
        for (int u = tid; u < SZ_A / 16; u += 512) dst[u] = src[u];
    }

    // ldmatrix lane bases
    const u32 aBase = smb + S_A + (u32)((wm * 32 + (lane & 15)) * A_ROWB + (lane >> 4) * 16);
    const int nl = wn * 32 + lane;                 // lane's n
    const int bi = nl >> 4, bj = nl & 15;
    const u32 bOff = (u32)(bi * 8 * XT_STRIDE + bj * 16);
    const int g_  = lane >> 2;
    const int tig = lane & 3;

    // ---- prologue: prefetch first tile ----
    const int ti0 = blockIdx.x;
    {
        const int i0 = (ti0 >> 5) * TILE, j0 = (ti0 & 31) * TILE;
        for (int u = tid; u < XT_ROWS * 19; u += 512) {
            const int r = u / 19, ch = u - r * 19;
            const int gr = i0 + r, gc = j0 + ch * 8;
            const u32 dsa = smb + S_X + (u32)(r * XT_STRIDE + ch * 16);
            if (gr < IN_DIM && gc < IN_DIM) {
                CP16(dsa, g_x16 + (size_t)gr * IN_DIM + gc);
            } else {
                *reinterpret_cast<uint4*>(sm + S_X + r * XT_STRIDE + ch * 16) = make_uint4(0, 0, 0, 0);
            }
        }
        CPCOMMIT();
    }

    int it = 0;
    for (int ti = ti0; ti < NTILES; ti += gridDim.x, ++it) {
        const int cur = it & 1;
        const int i0 = (ti >> 5) * TILE, j0 = (ti & 31) * TILE;

        // prefetch next tile into other buffer (previous consumers passed the end barrier)
        const int tn = ti + gridDim.x;
        if (tn < NTILES) {
            const int ni0 = (tn >> 5) * TILE, nj0 = (tn & 31) * TILE;
            const u32 nb = smb + S_X + (u32)((cur ^ 1) * SZ_X);
            for (int u = tid; u < XT_ROWS * 19; u += 512) {
                const int r = u / 19, ch = u - r * 19;
                const int gr = ni0 + r, gc = nj0 + ch * 8;
                const u32 dsa = nb + (u32)(r * XT_STRIDE + ch * 16);
                if (gr < IN_DIM && gc < IN_DIM) {
                    CP16(dsa, g_x16 + (size_t)gr * IN_DIM + gc);
                } else {
                    *reinterpret_cast<uint4*>(sm + (dsa - smb)) = make_uint4(0, 0, 0, 0);
                }
            }
            CPCOMMIT();
            CPWAIT1();           // current tile's group done; next still in flight
        } else {
            CPWAIT0();
        }
        __syncthreads();

        // ---- mainloop: 36 k16 chunks ----
        float acc[2][4][4];
        #pragma unroll
        for (int a = 0; a < 2; ++a)
            #pragma unroll
            for (int b = 0; b < 4; ++b)
                #pragma unroll
                for (int i = 0; i < 4; ++i) acc[a][b][i] = 0.f;

        const u32 bBase = smb + S_X + (u32)(cur * SZ_X) + bOff;

        #pragma unroll
        for (int c = 0; c < NCHUNK; ++c) {
            const int o0 = 2 * c, o1 = 2 * c + 1;
            const int p0 = o0 / 3, t0 = o0 - p0 * 3;
            const int p1 = o1 / 3, t1 = o1 - p1 * 3;
            u32 aF0[4], aF1[4], bL[4], bH[4];
            LDSM4(aF0, aBase + (u32)(c * 64 * A_ROWB));
            LDSM4(aF1, aBase + (u32)(c * 64 * A_ROWB + 16 * A_ROWB));
            LDSM4(bL, bBase + (u32)(p0 * XT_STRIDE + t0 * 16));
            LDSM4(bH, bBase + (u32)(p1 * XT_STRIDE + t1 * 16));
            #pragma unroll
            for (int nt = 0; nt < 4; ++nt) {
                MMA16(acc[0][nt], aF0, bL[nt], bH[nt]);
                MMA16(acc[1][nt], aF1, bL[nt], bH[nt]);
            }
        }

        // ---- epilogue: direct STG (8-contiguous per lane-octet) ----
        #pragma unroll
        for (int mt = 0; mt < 2; ++mt)
            #pragma unroll
            for (int nt = 0; nt < 4; ++nt)
                #pragma unroll
                for (int i = 0; i < 4; ++i) {
                    const int m = wm * 32 + mt * 16 + g_ + ((i >> 1) ? 8 : 0);
                    const int n = wn * 32 + nt * 8 + tig * 2 + (i & 1);
                    const int rl = ((n >> 4) << 3) + (m >> 3);
                    const int cl = ((n & 15) << 3) + (m & 7);
                    const int gr = i0 + rl, gc = j0 + cl;
                    if (gr < OUT_DIM && gc < OUT_DIM)
                        out[(size_t)gr * OUT_DIM + gc] = acc[mt][nt][i] + bv;
                }
        __syncthreads();    // all reads of buf cur done before it becomes prefetch target
    }
}

// ============ launch ============
extern "C" void kernel_launch(void* const* d_in, const int* in_sizes, int n_in,
                              void* d_out, int out_size)
{
    (void)in_sizes; (void)n_in; (void)out_size;
    const float* x    = (const float*)d_in[0];
    const float* w    = (const float*)d_in[1];
    const float* bias = (const float*)d_in[2];
    float* out        = (float*)d_out;

    cudaFuncSetAttribute(conv_hmma_kernel,
                         cudaFuncAttributeMaxDynamicSharedMemorySize, SMEM_TOTAL);

    convert_x_kernel<<<(IN_DIM * (size_t)IN_DIM) / (256 * 8), 256>>>(x);
    prep_a_kernel<<<216, 256>>>(w);                       // 55296 elems
    conv_hmma_kernel<<<152, 512, SMEM_TOTAL>>>(bias, out);
}

// round 17
// speedup vs baseline: 1.4125x; 1.4125x over previous
#include <cuda_runtime.h>
#include <cuda_fp16.h>
#include <cstdint>

typedef unsigned int u32;

#define IN_DIM   4096
#define OUT_DIM  4081
#define TILE     128           // square output tile
#define NTILES   1024          // 32 x 32
#define XT_ROWS  144           // 128 + 16 halo
#define XT_STRIDE 304          // bytes per x-tile row (152 halves)
#define NCHUNK   36            // k16 chunks = 72 octets paired

// A: [36 chunks][64 m][24 halves (16 data + 8 pad)] -> 48 B/row, conflict-free ldmatrix
#define A_ROWB   48
#define SZ_A     (NCHUNK * 64 * A_ROWB)     // 110592
#define SZ_X     (XT_ROWS * XT_STRIDE)      // 43776
#define S_A      0
#define S_X      SZ_A
#define SMEM_TOTAL (SZ_A + 2 * SZ_X)        // 198144

__device__ __half g_x16[(size_t)IN_DIM * IN_DIM];
__device__ __half g_A[SZ_A / 2];

__device__ __forceinline__ u32 smem_u32(const void* p) {
    u32 a;
    asm("{ .reg .u64 t; cvta.to.shared.u64 t, %1; cvt.u32.u64 %0, t; }" : "=r"(a) : "l"(p));
    return a;
}

#define LDSM4(r, a) \
    asm volatile("ldmatrix.sync.aligned.m8n8.x4.shared.b16 {%0,%1,%2,%3}, [%4];" \
        : "=r"((r)[0]), "=r"((r)[1]), "=r"((r)[2]), "=r"((r)[3]) : "r"(a))

#define MMA16(d, a, b0, b1) \
    asm volatile("mma.sync.aligned.m16n8k16.row.col.f32.f16.f16.f32 " \
        "{%0,%1,%2,%3}, {%4,%5,%6,%7}, {%8,%9}, {%0,%1,%2,%3};" \
        : "+f"((d)[0]), "+f"((d)[1]), "+f"((d)[2]), "+f"((d)[3]) \
        : "r"((a)[0]), "r"((a)[1]), "r"((a)[2]), "r"((a)[3]), "r"(b0), "r"(b1))

#define CP16(dst, src)  asm volatile("cp.async.cg.shared.global [%0], [%1], 16;" :: "r"(dst), "l"(src))
#define CPCOMMIT()      asm volatile("cp.async.commit_group;" ::: "memory")
#define CPWAIT0()       asm volatile("cp.async.wait_group 0;" ::: "memory")
#define CPWAIT1()       asm volatile("cp.async.wait_group 1;" ::: "memory")

// ============ prep: x fp32 -> fp16 (16 elems/thread) ============
__global__ void convert_x_kernel(const float* __restrict__ x) {
    size_t base = ((size_t)blockIdx.x * 256u + threadIdx.x) * 16u;
    float4 v0 = *reinterpret_cast<const float4*>(x + base);
    float4 v1 = *reinterpret_cast<const float4*>(x + base + 4);
    float4 v2 = *reinterpret_cast<const float4*>(x + base + 8);
    float4 v3 = *reinterpret_cast<const float4*>(x + base + 12);
    u32 r[8];
    r[0] = (u32)__half_as_ushort(__float2half(v0.x)) | ((u32)__half_as_ushort(__float2half(v0.y)) << 16);
    r[1] = (u32)__half_as_ushort(__float2half(v0.z)) | ((u32)__half_as_ushort(__float2half(v0.w)) << 16);
    r[2] = (u32)__half_as_ushort(__float2half(v1.x)) | ((u32)__half_as_ushort(__float2half(v1.y)) << 16);
    r[3] = (u32)__half_as_ushort(__float2half(v1.z)) | ((u32)__half_as_ushort(__float2half(v1.w)) << 16);
    r[4] = (u32)__half_as_ushort(__float2half(v2.x)) | ((u32)__half_as_ushort(__float2half(v2.y)) << 16);
    r[5] = (u32)__half_as_ushort(__float2half(v2.z)) | ((u32)__half_as_ushort(__float2half(v2.w)) << 16);
    r[6] = (u32)__half_as_ushort(__float2half(v3.x)) | ((u32)__half_as_ushort(__float2half(v3.y)) << 16);
    r[7] = (u32)__half_as_ushort(__float2half(v3.z)) | ((u32)__half_as_ushort(__float2half(v3.w)) << 16);
    *reinterpret_cast<uint4*>(g_x16 + base)     = make_uint4(r[0], r[1], r[2], r[3]);
    *reinterpret_cast<uint4*>(g_x16 + base + 8) = make_uint4(r[4], r[5], r[6], r[7]);
}

// ============ prep: shifted-weight A, k16-paired octets, 48B pitch ============
__global__ void prep_a_kernel(const float* __restrict__ w) {
    int e = blockIdx.x * 256 + threadIdx.x;        // [0, 55296)
    int c   = e / (64 * 24);
    int rem = e - c * (64 * 24);
    int m   = rem / 24;
    int kk  = rem - m * 24;
    float v = 0.0f;
    if (kk < 16) {
        int o  = 2 * c + (kk >> 3);
        int p  = o / 3;
        int q  = (o - p * 3) * 8 + (kk & 7);
        int di = m >> 3, dj = m & 7;
        int pi = p - di, qi = q - dj;
        if (pi >= 0 && pi < 16 && qi >= 0 && qi < 16) v = w[pi * 16 + qi];
    }
    g_A[e] = __float2half(v);
}

// B smem byte offset (relative to buffer base + lane bOff) for chunk c, half h
__device__ __forceinline__ constexpr u32 bChunkOff(int c, int h) {
    const int o = 2 * c + h;
    const int p = o / 3;
    const int t = o - p * 3;
    return (u32)(p * XT_STRIDE + t * 16);
}

// ============ main: persistent k16 implicit-GEMM conv ============
__global__ __launch_bounds__(512, 1)
void conv_hmma_kernel(const float* __restrict__ bias, float* __restrict__ out)
{
    extern __shared__ char sm[];
    const u32 smb  = smem_u32(sm);
    const int tid  = threadIdx.x;
    const int lane = tid & 31;
    const int wid  = tid >> 5;
    const int wm   = wid >> 3;        // 0..1  (M half)
    const int wn   = wid & 7;         // 0..7  (N 32-group)
    const float bv = bias[0];

    // ---- stage A once per CTA lifetime ----
    {
        const uint4* src = reinterpret_cast<const uint4*>(g_A);
        uint4* dst = reinterpret_cast<uint4*>(sm + S_A);
        for (int u = tid; u < SZ_A / 16; u += 512) dst[u] = src[u];
    }

    // ldmatrix lane bases
    const u32 aBase = smb + S_A + (u32)((wm * 32 + (lane & 15)) * A_ROWB + (lane >> 4) * 16);
    const int nl = wn * 32 + lane;
    const int bi = nl >> 4, bj = nl & 15;
    const u32 bOff = (u32)(bi * 8 * XT_STRIDE + bj * 16);
    const int g_  = lane >> 2;
    const int tig = lane & 3;

    // ---- prologue: prefetch first tile ----
    const int ti0 = blockIdx.x;
    {
        const int i0 = (ti0 >> 5) * TILE, j0 = (ti0 & 31) * TILE;
        for (int u = tid; u < XT_ROWS * 19; u += 512) {
            const int r = u / 19, ch = u - r * 19;
            const int gr = i0 + r, gc = j0 + ch * 8;
            const u32 dsa = smb + S_X + (u32)(r * XT_STRIDE + ch * 16);
            if (gr < IN_DIM && gc < IN_DIM) {
                CP16(dsa, g_x16 + (size_t)gr * IN_DIM + gc);
            } else {
                *reinterpret_cast<uint4*>(sm + S_X + r * XT_STRIDE + ch * 16) = make_uint4(0, 0, 0, 0);
            }
        }
        CPCOMMIT();
    }

    int it = 0;
    for (int ti = ti0; ti < NTILES; ti += gridDim.x, ++it) {
        const int cur = it & 1;
        const int i0 = (ti >> 5) * TILE, j0 = (ti & 31) * TILE;

        // prefetch next tile into other buffer
        const int tn = ti + gridDim.x;
        if (tn < NTILES) {
            const int ni0 = (tn >> 5) * TILE, nj0 = (tn & 31) * TILE;
            const u32 nb = smb + S_X + (u32)((cur ^ 1) * SZ_X);
            for (int u = tid; u < XT_ROWS * 19; u += 512) {
                const int r = u / 19, ch = u - r * 19;
                const int gr = ni0 + r, gc = nj0 + ch * 8;
                const u32 dsa = nb + (u32)(r * XT_STRIDE + ch * 16);
                if (gr < IN_DIM && gc < IN_DIM) {
                    CP16(dsa, g_x16 + (size_t)gr * IN_DIM + gc);
                } else {
                    *reinterpret_cast<uint4*>(sm + (dsa - smb)) = make_uint4(0, 0, 0, 0);
                }
            }
            CPCOMMIT();
            CPWAIT1();
        } else {
            CPWAIT0();
        }
        __syncthreads();

        // ---- fully-unrolled, fragment-double-buffered mainloop: 36 k16 chunks ----
        float acc[2][4][4];
        #pragma unroll
        for (int a = 0; a < 2; ++a)
            #pragma unroll
            for (int b = 0; b < 4; ++b)
                #pragma unroll
                for (int i = 0; i < 4; ++i) acc[a][b][i] = 0.f;

        const u32 bBase = smb + S_X + (u32)(cur * SZ_X) + bOff;

        u32 fA0[2][4], fA1[2][4], fBL[2][4], fBH[2][4];
        LDSM4(fA0[0], aBase);
        LDSM4(fA1[0], aBase + 16 * A_ROWB);
        LDSM4(fBL[0], bBase + bChunkOff(0, 0));
        LDSM4(fBH[0], bBase + bChunkOff(0, 1));

        #pragma unroll
        for (int c = 0; c < NCHUNK; ++c) {
            const int cb = c & 1, nb_ = cb ^ 1;
            if (c < NCHUNK - 1) {
                LDSM4(fA0[nb_], aBase + (u32)((c + 1) * 64 * A_ROWB));
                LDSM4(fA1[nb_], aBase + (u32)((c + 1) * 64 * A_ROWB + 16 * A_ROWB));
                LDSM4(fBL[nb_], bBase + bChunkOff(c + 1, 0));
                LDSM4(fBH[nb_], bBase + bChunkOff(c + 1, 1));
            }
            #pragma unroll
            for (int nt = 0; nt < 4; ++nt) {
                MMA16(acc[0][nt], fA0[cb], fBL[cb][nt], fBH[cb][nt]);
                MMA16(acc[1][nt], fA1[cb], fBL[cb][nt], fBH[cb][nt]);
            }
        }

        // ---- epilogue: direct STG ----
        #pragma unroll
        for (int mt = 0; mt < 2; ++mt)
            #pragma unroll
            for (int nt = 0; nt < 4; ++nt)
                #pragma unroll
                for (int i = 0; i < 4; ++i) {
                    const int m = wm * 32 + mt * 16 + g_ + ((i >> 1) ? 8 : 0);
                    const int n = wn * 32 + nt * 8 + tig * 2 + (i & 1);
                    const int rl = ((n >> 4) << 3) + (m >> 3);
                    const int cl = ((n & 15) << 3) + (m & 7);
                    const int gr = i0 + rl, gc = j0 + cl;
                    if (gr < OUT_DIM && gc < OUT_DIM)
                        out[(size_t)gr * OUT_DIM + gc] = acc[mt][nt][i] + bv;
                }
        __syncthreads();
    }
}

// ============ launch ============
extern "C" void kernel_launch(void* const* d_in, const int* in_sizes, int n_in,
                              void* d_out, int out_size)
{
    (void)in_sizes; (void)n_in; (void)out_size;
    const float* x    = (const float*)d_in[0];
    const float* w    = (const float*)d_in[1];
    const float* bias = (const float*)d_in[2];
    float* out        = (float*)d_out;

    cudaFuncSetAttribute(conv_hmma_kernel,
                         cudaFuncAttributeMaxDynamicSharedMemorySize, SMEM_TOTAL);

    convert_x_kernel<<<(IN_DIM * (size_t)IN_DIM) / (256 * 16), 256>>>(x);
    prep_a_kernel<<<216, 256>>>(w);
    conv_hmma_kernel<<<152, 512, SMEM_TOTAL>>>(bias, out);
}